// round 3
// baseline (speedup 1.0000x reference)
#include <cuda_runtime.h>

// GraphLayer: B=8, N=4096, Cin=64, Cout=128, K=16
//  k0: sqnorm per point + zero BN stat accumulators
//  k1: fused scores-GEMM + streaming top-16 + gather + maxpool -> g_pooled
//  k2: pooled @ W^T + bias -> d_out (pre-BN) + per-channel sum/sumsq atomics
//  k2b: finalize BN scale/shift
//  k3: in-place normalize + ReLU on d_out

#define BSZ   8
#define NPTS  4096
#define CIN   64
#define COUT  128
#define KNN   16
#define MTOT  (BSZ * NPTS)          // 32768

#define QT    128                   // queries per block (kernel 1)
#define CT    64                    // candidates per tile
#define PAD_A 68                    // float4-aligned pad for x tiles
#define PAD_S 65                    // odd pad for score tile (conflict-free row scan)

__device__ float g_sqnorm[MTOT];
__device__ float g_pooled[(size_t)MTOT * CIN];   // 8 MB scratch
__device__ float g_sum[COUT];
__device__ float g_sumsq[COUT];
__device__ float g_scale[COUT];
__device__ float g_shift[COUT];

// ---------------------------------------------------------------- kernel 0
__global__ void k_sqnorm(const float* __restrict__ x) {
    int p = blockIdx.x * blockDim.x + threadIdx.x;
    if (p < MTOT) {
        const float4* r = (const float4*)(x + (size_t)p * CIN);
        float s = 0.f;
        #pragma unroll
        for (int i = 0; i < CIN / 4; i++) {
            float4 v = r[i];
            s += v.x * v.x + v.y * v.y + v.z * v.z + v.w * v.w;
        }
        g_sqnorm[p] = s;
    }
    if (p < COUT) { g_sum[p] = 0.f; g_sumsq[p] = 0.f; }
}

// ---------------------------------------------------------------- kernel 1
// grid (NPTS/QT, BSZ), 256 threads.
__global__ __launch_bounds__(256)
void k_knn_pool(const float* __restrict__ x) {
    extern __shared__ float sh[];
    float* As  = sh;                        // [QT][PAD_A]
    float* Bs  = As + QT * PAD_A;           // [CT][PAD_A]
    float* Ss  = Bs + CT * PAD_A;           // [QT][PAD_S]  (reused as int idx later)
    float* sqc = Ss + QT * PAD_S;           // [CT]

    const int tid = threadIdx.x;
    const int tx = tid & 15, ty = tid >> 4;
    const int b  = blockIdx.y;
    const int q0 = blockIdx.x * QT;
    const float* xb = x + (size_t)b * NPTS * CIN;

    // load query tile (once; first in-loop __syncthreads covers it)
    {
        const float4* src = (const float4*)(xb + (size_t)q0 * CIN);
        #pragma unroll
        for (int t = 0; t < (QT * CIN / 4) / 256; t++) {
            int id = tid + t * 256;               // 0..2047
            int row = id >> 4, c4 = (id & 15) << 2;
            *(float4*)&As[row * PAD_A + c4] = src[id];
        }
    }

    float kval[KNN]; int kidx[KNN];
    #pragma unroll
    for (int i = 0; i < KNN; i++) { kval[i] = 3.4e38f; kidx[i] = 0; }

    for (int tile = 0; tile < NPTS / CT; ++tile) {
        // load candidate tile + its sqnorms
        {
            const float4* src = (const float4*)(xb + (size_t)tile * CT * CIN);
            #pragma unroll
            for (int t = 0; t < (CT * CIN / 4) / 256; t++) {
                int id = tid + t * 256;           // 0..1023
                int row = id >> 4, c4 = (id & 15) << 2;
                *(float4*)&Bs[row * PAD_A + c4] = src[id];
            }
            if (tid < CT) sqc[tid] = g_sqnorm[b * NPTS + tile * CT + tid];
        }
        __syncthreads();

        // 128x64 score tile: acc[i][j] = x_q . x_c
        float acc[8][4];
        #pragma unroll
        for (int i = 0; i < 8; i++)
            #pragma unroll
            for (int j = 0; j < 4; j++) acc[i][j] = 0.f;

        #pragma unroll 4
        for (int k = 0; k < CIN; k++) {
            float a[8], bb[4];
            #pragma unroll
            for (int i = 0; i < 8; i++) a[i] = As[(ty + 16 * i) * PAD_A + k];
            #pragma unroll
            for (int j = 0; j < 4; j++) bb[j] = Bs[(tx + 16 * j) * PAD_A + k];
            #pragma unroll
            for (int i = 0; i < 8; i++)
                #pragma unroll
                for (int j = 0; j < 4; j++)
                    acc[i][j] = fmaf(a[i], bb[j], acc[i][j]);
        }

        // keys: ||x_c||^2 - 2 dot   (ordering == squared distance ordering)
        #pragma unroll
        for (int i = 0; i < 8; i++) {
            int r = ty + 16 * i;
            #pragma unroll
            for (int j = 0; j < 4; j++) {
                int c = tx + 16 * j;
                Ss[r * PAD_S + c] = fmaf(-2.f, acc[i][j], sqc[c]);
            }
        }
        __syncthreads();

        // streaming top-16 per query (thread tid scans query row tid)
        if (tid < QT) {
            int base = tile * CT;
            #pragma unroll 4
            for (int j = 0; j < CT; j++) {
                float key = Ss[tid * PAD_S + j];
                if (key < kval[KNN - 1]) {
                    kval[KNN - 1] = key; kidx[KNN - 1] = base + j;
                    #pragma unroll
                    for (int t = KNN - 1; t > 0; --t) {
                        if (kval[t] < kval[t - 1]) {
                            float tv = kval[t]; kval[t] = kval[t - 1]; kval[t - 1] = tv;
                            int   ti = kidx[t]; kidx[t] = kidx[t - 1]; kidx[t - 1] = ti;
                        }
                    }
                }
            }
        }
        __syncthreads();
    }

    // share indices, then warp-cooperative gather + maxpool (coalesced row loads)
    int* sidx = (int*)Ss;
    if (tid < QT) {
        #pragma unroll
        for (int i = 0; i < KNN; i++) sidx[tid * KNN + i] = kidx[i];
    }
    __syncthreads();

    const int w = tid >> 5, lane = tid & 31;
    for (int qq = w * 16; qq < w * 16 + 16; ++qq) {
        float m0 = -3.4e38f, m1 = -3.4e38f;
        #pragma unroll
        for (int i = 0; i < KNN; i++) {
            int nb = sidx[qq * KNN + i];
            const float* row = xb + (size_t)nb * CIN;
            m0 = fmaxf(m0, row[lane]);
            m1 = fmaxf(m1, row[lane + 32]);
        }
        float* outp = g_pooled + (size_t)(b * NPTS + q0 + qq) * CIN;
        outp[lane] = m0; outp[lane + 32] = m1;
    }
}

// ---------------------------------------------------------------- kernel 2
// grid (MTOT/128), 256 threads: y = pooled @ W^T + b, write d_out, accumulate stats
__global__ __launch_bounds__(256)
void k_gemm_stats(const float* __restrict__ W, const float* __restrict__ bias,
                  float* __restrict__ out) {
    extern __shared__ float sh[];
    float* Ps   = sh;                     // [128][PAD_A]
    float* Ws   = Ps + 128 * PAD_A;       // [128][PAD_A]
    float* ssum = Ws + 128 * PAD_A;       // [COUT]
    float* ssq  = ssum + COUT;            // [COUT]

    const int tid = threadIdx.x;
    const int tx = tid & 15, ty = tid >> 4;
    const int row0 = blockIdx.x * 128;

    {
        const float4* src = (const float4*)(g_pooled + (size_t)row0 * CIN);
        #pragma unroll
        for (int t = 0; t < 8; t++) {
            int id = tid + t * 256;
            int r = id >> 4, c4 = (id & 15) << 2;
            *(float4*)&Ps[r * PAD_A + c4] = src[id];
        }
        const float4* wsrc = (const float4*)W;
        #pragma unroll
        for (int t = 0; t < 8; t++) {
            int id = tid + t * 256;
            int r = id >> 4, c4 = (id & 15) << 2;
            *(float4*)&Ws[r * PAD_A + c4] = wsrc[id];
        }
        if (tid < COUT) { ssum[tid] = 0.f; ssq[tid] = 0.f; }
    }
    __syncthreads();

    float acc[8][8];
    #pragma unroll
    for (int i = 0; i < 8; i++)
        #pragma unroll
        for (int j = 0; j < 8; j++) acc[i][j] = 0.f;

    #pragma unroll 4
    for (int k = 0; k < CIN; k++) {
        float a[8], bb[8];
        #pragma unroll
        for (int i = 0; i < 8; i++) a[i] = Ps[(ty + 16 * i) * PAD_A + k];
        #pragma unroll
        for (int j = 0; j < 8; j++) bb[j] = Ws[(tx + 16 * j) * PAD_A + k];
        #pragma unroll
        for (int i = 0; i < 8; i++)
            #pragma unroll
            for (int j = 0; j < 8; j++)
                acc[i][j] = fmaf(a[i], bb[j], acc[i][j]);
    }

    float ls[8], lq[8];
    #pragma unroll
    for (int j = 0; j < 8; j++) { ls[j] = 0.f; lq[j] = 0.f; }

    #pragma unroll
    for (int j = 0; j < 8; j++) {
        int c = tx + 16 * j;
        float bj = bias[c];
        #pragma unroll
        for (int i = 0; i < 8; i++) {
            int r = row0 + ty + 16 * i;
            float y = acc[i][j] + bj;
            out[(size_t)r * COUT + c] = y;
            ls[j] += y;
            lq[j] = fmaf(y, y, lq[j]);
        }
    }
    #pragma unroll
    for (int j = 0; j < 8; j++) {
        int c = tx + 16 * j;
        atomicAdd(&ssum[c], ls[j]);
        atomicAdd(&ssq[c],  lq[j]);
    }
    __syncthreads();
    if (tid < COUT) {
        atomicAdd(&g_sum[tid],   ssum[tid]);
        atomicAdd(&g_sumsq[tid], ssq[tid]);
    }
}

// ---------------------------------------------------------------- kernel 2b
__global__ void k_finalize(const float* __restrict__ gamma,
                           const float* __restrict__ beta) {
    int c = threadIdx.x;
    if (c < COUT) {
        const float invM = 1.f / (float)MTOT;
        float m = g_sum[c] * invM;
        float v = fmaf(-m, m, g_sumsq[c] * invM);
        float sc = gamma[c] * rsqrtf(v + 1e-5f);
        g_scale[c] = sc;
        g_shift[c] = fmaf(-m, sc, beta[c]);
    }
}

// ---------------------------------------------------------------- kernel 3
__global__ void k_apply(float* __restrict__ out) {
    int i = blockIdx.x * blockDim.x + threadIdx.x;        // float4 index
    if (i < MTOT * COUT / 4) {
        float4 v = ((float4*)out)[i];
        int c = (i * 4) & (COUT - 1);
        v.x = fmaxf(0.f, fmaf(v.x, g_scale[c],     g_shift[c]));
        v.y = fmaxf(0.f, fmaf(v.y, g_scale[c + 1], g_shift[c + 1]));
        v.z = fmaxf(0.f, fmaf(v.z, g_scale[c + 2], g_shift[c + 2]));
        v.w = fmaxf(0.f, fmaf(v.w, g_scale[c + 3], g_shift[c + 3]));
        ((float4*)out)[i] = v;
    }
}

// ---------------------------------------------------------------- launch
extern "C" void kernel_launch(void* const* d_in, const int* in_sizes, int n_in,
                              void* d_out, int out_size) {
    const float* x     = (const float*)d_in[0];
    const float* W     = (const float*)d_in[1];
    const float* bias  = (const float*)d_in[2];
    const float* gamma = (const float*)d_in[3];
    const float* beta  = (const float*)d_in[4];
    float* out = (float*)d_out;

    const int smem1 = (QT * PAD_A + CT * PAD_A + QT * PAD_S + CT) * 4;   // 85760 B
    const int smem2 = (128 * PAD_A * 2 + 2 * COUT) * 4;                  // 70656 B
    cudaFuncSetAttribute(k_knn_pool,   cudaFuncAttributeMaxDynamicSharedMemorySize, smem1);
    cudaFuncSetAttribute(k_gemm_stats, cudaFuncAttributeMaxDynamicSharedMemorySize, smem2);

    k_sqnorm<<<(MTOT + 255) / 256, 256>>>(x);
    k_knn_pool<<<dim3(NPTS / QT, BSZ), 256, smem1>>>(x);
    k_gemm_stats<<<MTOT / 128, 256, smem2>>>(W, bias, out);
    k_finalize<<<1, COUT>>>(gamma, beta);
    k_apply<<<(MTOT * COUT / 4 + 255) / 256, 256>>>(out);
}

// round 4
// speedup vs baseline: 1.0138x; 1.0138x over previous
#include <cuda_runtime.h>

// GraphLayer: B=8, N=4096, Cin=64, Cout=128, K=16
//  k0: sqnorm per point + zero BN stat accumulators
//  k1: fused scores-GEMM (packed f32x2 FFMA2) + streaming top-16 + gather/maxpool
//  k2: pooled @ W^T + bias -> d_out (pre-BN) + per-channel sum/sumsq atomics
//  k2b: finalize BN scale/shift
//  k3: in-place normalize + ReLU on d_out

#define BSZ   8
#define NPTS  4096
#define CIN   64
#define COUT  128
#define KNN   16
#define MTOT  (BSZ * NPTS)          // 32768

#define QT    128                   // queries per block (kernel 1)
#define CT    64                    // candidates per tile
#define RQ    132                   // k-major query tile row length (16B-aligned rows)
#define RC    68                    // k-major cand  tile row length (16B-aligned rows)
#define PAD_A 68                    // pad for kernel-2 tiles
#define PAD_S 65                    // odd pad for score tile

__device__ float g_sqnorm[MTOT];
__device__ float g_pooled[(size_t)MTOT * CIN];   // 8 MB scratch
__device__ float g_sum[COUT];
__device__ float g_sumsq[COUT];
__device__ float g_scale[COUT];
__device__ float g_shift[COUT];

// ---- packed fp32x2 helpers (sm_103a dual-fp32 path; ptxas never auto-emits) ----
__device__ __forceinline__ unsigned long long pack2(float lo, float hi) {
    unsigned long long r;
    asm("mov.b64 %0, {%1, %2};" : "=l"(r) : "f"(lo), "f"(hi));
    return r;
}
__device__ __forceinline__ void fma2(unsigned long long& d,
                                     unsigned long long a, unsigned long long b) {
    asm("fma.rn.f32x2 %0, %1, %2, %0;" : "+l"(d) : "l"(a), "l"(b));
}
__device__ __forceinline__ void unpack2(float& lo, float& hi, unsigned long long v) {
    asm("mov.b64 {%0, %1}, %2;" : "=f"(lo), "=f"(hi) : "l"(v));
}

// ---------------------------------------------------------------- kernel 0
__global__ void k_sqnorm(const float* __restrict__ x) {
    int p = blockIdx.x * blockDim.x + threadIdx.x;
    if (p < MTOT) {
        const float4* r = (const float4*)(x + (size_t)p * CIN);
        float s = 0.f;
        #pragma unroll
        for (int i = 0; i < CIN / 4; i++) {
            float4 v = r[i];
            s += v.x * v.x + v.y * v.y + v.z * v.z + v.w * v.w;
        }
        g_sqnorm[p] = s;
    }
    if (p < COUT) { g_sum[p] = 0.f; g_sumsq[p] = 0.f; }
}

// ---------------------------------------------------------------- kernel 1
// grid (NPTS/QT, BSZ), 256 threads. k-major SMEM tiles feed f32x2 FMAs.
__global__ __launch_bounds__(256)
void k_knn_pool(const float* __restrict__ x) {
    extern __shared__ float sh[];
    float* AsT = sh;                        // [CIN][RQ]  (k-major queries)
    float* BsT = AsT + CIN * RQ;            // [CIN][RC]  (k-major candidates)
    float* Ss  = BsT + CIN * RC;            // [QT][PAD_S] (reused as int idx later)
    float* sqc = Ss + QT * PAD_S;           // [CT]

    const int tid = threadIdx.x;
    const int tx = tid & 15, ty = tid >> 4;
    const int b  = blockIdx.y;
    const int q0 = blockIdx.x * QT;
    const float* xb = x + (size_t)b * NPTS * CIN;

    // load query tile (once), transposed to k-major
    {
        const float4* src = (const float4*)(xb + (size_t)q0 * CIN);
        #pragma unroll
        for (int t = 0; t < (QT * CIN / 4) / 256; t++) {
            int id = tid + t * 256;               // 0..2047
            int q = id >> 4, k4 = (id & 15) << 2;
            float4 v = src[id];
            AsT[(k4 + 0) * RQ + q] = v.x;
            AsT[(k4 + 1) * RQ + q] = v.y;
            AsT[(k4 + 2) * RQ + q] = v.z;
            AsT[(k4 + 3) * RQ + q] = v.w;
        }
    }

    float kval[KNN]; int kidx[KNN];
    #pragma unroll
    for (int i = 0; i < KNN; i++) { kval[i] = 3.4e38f; kidx[i] = 0; }

    for (int tile = 0; tile < NPTS / CT; ++tile) {
        // load candidate tile transposed + its sqnorms
        {
            const float4* src = (const float4*)(xb + (size_t)tile * CT * CIN);
            #pragma unroll
            for (int t = 0; t < (CT * CIN / 4) / 256; t++) {
                int id = tid + t * 256;           // 0..1023
                int c = id >> 4, k4 = (id & 15) << 2;
                float4 v = src[id];
                BsT[(k4 + 0) * RC + c] = v.x;
                BsT[(k4 + 1) * RC + c] = v.y;
                BsT[(k4 + 2) * RC + c] = v.z;
                BsT[(k4 + 3) * RC + c] = v.w;
            }
            if (tid < CT) sqc[tid] = g_sqnorm[b * NPTS + tile * CT + tid];
        }
        __syncthreads();

        // 128x64 score tile via packed f32x2:
        // thread (tx,ty): queries ty*8..ty*8+7 (4 pairs), candidates tx*4..tx*4+3
        unsigned long long acc[4][4];
        #pragma unroll
        for (int p = 0; p < 4; p++)
            #pragma unroll
            for (int j = 0; j < 4; j++) acc[p][j] = 0ULL;

        #pragma unroll 4
        for (int k = 0; k < CIN; k++) {
            float4 a0 = *(const float4*)&AsT[k * RQ + ty * 8];
            float4 a1 = *(const float4*)&AsT[k * RQ + ty * 8 + 4];
            float4 bv = *(const float4*)&BsT[k * RC + tx * 4];
            unsigned long long ap[4], bp[4];
            ap[0] = pack2(a0.x, a0.y); ap[1] = pack2(a0.z, a0.w);
            ap[2] = pack2(a1.x, a1.y); ap[3] = pack2(a1.z, a1.w);
            bp[0] = pack2(bv.x, bv.x); bp[1] = pack2(bv.y, bv.y);
            bp[2] = pack2(bv.z, bv.z); bp[3] = pack2(bv.w, bv.w);
            #pragma unroll
            for (int p = 0; p < 4; p++)
                #pragma unroll
                for (int j = 0; j < 4; j++)
                    fma2(acc[p][j], ap[p], bp[j]);
        }

        // keys: ||x_c||^2 - 2 dot  (ordering == squared-distance ordering)
        #pragma unroll
        for (int j = 0; j < 4; j++) {
            int c = tx * 4 + j;
            float sq = sqc[c];
            #pragma unroll
            for (int p = 0; p < 4; p++) {
                float lo, hi;
                unpack2(lo, hi, acc[p][j]);
                int r = ty * 8 + 2 * p;
                Ss[r * PAD_S + c]       = fmaf(-2.f, lo, sq);
                Ss[(r + 1) * PAD_S + c] = fmaf(-2.f, hi, sq);
            }
        }
        __syncthreads();

        // streaming top-16 per query (thread tid scans query row tid)
        if (tid < QT) {
            int base = tile * CT;
            #pragma unroll 4
            for (int j = 0; j < CT; j++) {
                float key = Ss[tid * PAD_S + j];
                if (key < kval[KNN - 1]) {
                    kval[KNN - 1] = key; kidx[KNN - 1] = base + j;
                    #pragma unroll
                    for (int t = KNN - 1; t > 0; --t) {
                        if (kval[t] < kval[t - 1]) {
                            float tv = kval[t]; kval[t] = kval[t - 1]; kval[t - 1] = tv;
                            int   ti = kidx[t]; kidx[t] = kidx[t - 1]; kidx[t - 1] = ti;
                        }
                    }
                }
            }
        }
        __syncthreads();
    }

    // share indices, then warp-cooperative gather + maxpool (coalesced row loads)
    int* sidx = (int*)Ss;
    if (tid < QT) {
        #pragma unroll
        for (int i = 0; i < KNN; i++) sidx[tid * KNN + i] = kidx[i];
    }
    __syncthreads();

    const int w = tid >> 5, lane = tid & 31;
    for (int qq = w * 16; qq < w * 16 + 16; ++qq) {
        float m0 = -3.4e38f, m1 = -3.4e38f;
        #pragma unroll
        for (int i = 0; i < KNN; i++) {
            int nb = sidx[qq * KNN + i];
            const float* row = xb + (size_t)nb * CIN;
            m0 = fmaxf(m0, row[lane]);
            m1 = fmaxf(m1, row[lane + 32]);
        }
        float* outp = g_pooled + (size_t)(b * NPTS + q0 + qq) * CIN;
        outp[lane] = m0; outp[lane + 32] = m1;
    }
}

// ---------------------------------------------------------------- kernel 2
// grid (MTOT/128), 256 threads: y = pooled @ W^T + b, write d_out, accumulate stats
__global__ __launch_bounds__(256)
void k_gemm_stats(const float* __restrict__ W, const float* __restrict__ bias,
                  float* __restrict__ out) {
    extern __shared__ float sh[];
    float* Ps   = sh;                     // [128][PAD_A]
    float* Ws   = Ps + 128 * PAD_A;       // [128][PAD_A]
    float* ssum = Ws + 128 * PAD_A;       // [COUT]
    float* ssq  = ssum + COUT;            // [COUT]

    const int tid = threadIdx.x;
    const int tx = tid & 15, ty = tid >> 4;
    const int row0 = blockIdx.x * 128;

    {
        const float4* src = (const float4*)(g_pooled + (size_t)row0 * CIN);
        #pragma unroll
        for (int t = 0; t < 8; t++) {
            int id = tid + t * 256;
            int r = id >> 4, c4 = (id & 15) << 2;
            *(float4*)&Ps[r * PAD_A + c4] = src[id];
        }
        const float4* wsrc = (const float4*)W;
        #pragma unroll
        for (int t = 0; t < 8; t++) {
            int id = tid + t * 256;
            int r = id >> 4, c4 = (id & 15) << 2;
            *(float4*)&Ws[r * PAD_A + c4] = wsrc[id];
        }
        if (tid < COUT) { ssum[tid] = 0.f; ssq[tid] = 0.f; }
    }
    __syncthreads();

    float acc[8][8];
    #pragma unroll
    for (int i = 0; i < 8; i++)
        #pragma unroll
        for (int j = 0; j < 8; j++) acc[i][j] = 0.f;

    #pragma unroll 4
    for (int k = 0; k < CIN; k++) {
        float a[8], bb[8];
        #pragma unroll
        for (int i = 0; i < 8; i++) a[i] = Ps[(ty + 16 * i) * PAD_A + k];
        #pragma unroll
        for (int j = 0; j < 8; j++) bb[j] = Ws[(tx + 16 * j) * PAD_A + k];
        #pragma unroll
        for (int i = 0; i < 8; i++)
            #pragma unroll
            for (int j = 0; j < 8; j++)
                acc[i][j] = fmaf(a[i], bb[j], acc[i][j]);
    }

    float ls[8], lq[8];
    #pragma unroll
    for (int j = 0; j < 8; j++) { ls[j] = 0.f; lq[j] = 0.f; }

    #pragma unroll
    for (int j = 0; j < 8; j++) {
        int c = tx + 16 * j;
        float bj = bias[c];
        #pragma unroll
        for (int i = 0; i < 8; i++) {
            int r = row0 + ty + 16 * i;
            float y = acc[i][j] + bj;
            out[(size_t)r * COUT + c] = y;
            ls[j] += y;
            lq[j] = fmaf(y, y, lq[j]);
        }
    }
    #pragma unroll
    for (int j = 0; j < 8; j++) {
        int c = tx + 16 * j;
        atomicAdd(&ssum[c], ls[j]);
        atomicAdd(&ssq[c],  lq[j]);
    }
    __syncthreads();
    if (tid < COUT) {
        atomicAdd(&g_sum[tid],   ssum[tid]);
        atomicAdd(&g_sumsq[tid], ssq[tid]);
    }
}

// ---------------------------------------------------------------- kernel 2b
__global__ void k_finalize(const float* __restrict__ gamma,
                           const float* __restrict__ beta) {
    int c = threadIdx.x;
    if (c < COUT) {
        const float invM = 1.f / (float)MTOT;
        float m = g_sum[c] * invM;
        float v = fmaf(-m, m, g_sumsq[c] * invM);
        float sc = gamma[c] * rsqrtf(v + 1e-5f);
        g_scale[c] = sc;
        g_shift[c] = fmaf(-m, sc, beta[c]);
    }
}

// ---------------------------------------------------------------- kernel 3
__global__ void k_apply(float* __restrict__ out) {
    int i = blockIdx.x * blockDim.x + threadIdx.x;        // float4 index
    if (i < MTOT * COUT / 4) {
        float4 v = ((float4*)out)[i];
        int c = (i * 4) & (COUT - 1);
        v.x = fmaxf(0.f, fmaf(v.x, g_scale[c],     g_shift[c]));
        v.y = fmaxf(0.f, fmaf(v.y, g_scale[c + 1], g_shift[c + 1]));
        v.z = fmaxf(0.f, fmaf(v.z, g_scale[c + 2], g_shift[c + 2]));
        v.w = fmaxf(0.f, fmaf(v.w, g_scale[c + 3], g_shift[c + 3]));
        ((float4*)out)[i] = v;
    }
}

// ---------------------------------------------------------------- launch
extern "C" void kernel_launch(void* const* d_in, const int* in_sizes, int n_in,
                              void* d_out, int out_size) {
    const float* x     = (const float*)d_in[0];
    const float* W     = (const float*)d_in[1];
    const float* bias  = (const float*)d_in[2];
    const float* gamma = (const float*)d_in[3];
    const float* beta  = (const float*)d_in[4];
    float* out = (float*)d_out;

    const int smem1 = (CIN * RQ + CIN * RC + QT * PAD_S + CT) * 4;       // 84736 B
    const int smem2 = (128 * PAD_A * 2 + 2 * COUT) * 4;                  // 70656 B
    cudaFuncSetAttribute(k_knn_pool,   cudaFuncAttributeMaxDynamicSharedMemorySize, smem1);
    cudaFuncSetAttribute(k_gemm_stats, cudaFuncAttributeMaxDynamicSharedMemorySize, smem2);

    k_sqnorm<<<(MTOT + 255) / 256, 256>>>(x);
    k_knn_pool<<<dim3(NPTS / QT, BSZ), 256, smem1>>>(x);
    k_gemm_stats<<<MTOT / 128, 256, smem2>>>(W, bias, out);
    k_finalize<<<1, COUT>>>(gamma, beta);
    k_apply<<<(MTOT * COUT / 4 + 255) / 256, 256>>>(out);
}

// round 7
// speedup vs baseline: 1.2484x; 1.2314x over previous
#include <cuda_runtime.h>
#include <cuda_bf16.h>
#include <cstdint>

// GraphLayer: B=8, N=4096, Cin=64, Cout=128, K=16
//  k_prep: sqnorm + split x into bf16 hi/lo + zero BN accumulators
//  k_knn_pool: HMMA bf16 split-precision Gram (filter) -> union of half top-16
//              -> exact fp32 key refine -> top-16 set -> gather/maxpool
//  k_gemm_stats / k_finalize / k_apply: conv1x1 + BN + ReLU

#define BSZ   8
#define NPTS  4096
#define CIN   64
#define COUT  128
#define KNN   16
#define MTOT  (BSZ * NPTS)          // 32768

#define QT    128                   // queries per CTA
#define CT    64                    // candidates per tile
#define NTILE (NPTS / CT)           // 64
#define PAD_S 65
#define PAD_A 68

__device__ float g_sqnorm[MTOT];
__device__ __nv_bfloat16 g_xhi[(size_t)MTOT * CIN];
__device__ __nv_bfloat16 g_xlo[(size_t)MTOT * CIN];
__device__ float g_pooled[(size_t)MTOT * CIN];
__device__ float g_sum[COUT];
__device__ float g_sumsq[COUT];
__device__ float g_scale[COUT];
__device__ float g_shift[COUT];

// ---- smem byte offsets for k1 ----
#define OFF_AHI 0
#define OFF_ALO 18432                 // 128*144
#define OFF_BHI 36864
#define OFF_BLO 46080                 // +64*144
#define OFF_SS  55296                 // score region: 128*65*4 = 33280
#define OFF_SQC 88576                 // 64*4
#define SMEM_K1 88832

__device__ __forceinline__ uint32_t smem_u32(const void* p) {
    uint32_t a;
    asm("{ .reg .u64 t; cvta.to.shared.u64 t, %1; cvt.u32.u64 %0, t; }" : "=r"(a) : "l"(p));
    return a;
}
__device__ __forceinline__ void ldmx4(uint32_t& r0, uint32_t& r1, uint32_t& r2,
                                      uint32_t& r3, uint32_t addr) {
    asm volatile("ldmatrix.sync.aligned.m8n8.x4.shared.b16 {%0,%1,%2,%3}, [%4];"
                 : "=r"(r0), "=r"(r1), "=r"(r2), "=r"(r3) : "r"(addr));
}
__device__ __forceinline__ void mma16816(float* c, const uint32_t* a,
                                         uint32_t b0, uint32_t b1) {
    asm volatile("mma.sync.aligned.m16n8k16.row.col.f32.bf16.bf16.f32 "
                 "{%0,%1,%2,%3}, {%4,%5,%6,%7}, {%8,%9}, {%0,%1,%2,%3};"
                 : "+f"(c[0]), "+f"(c[1]), "+f"(c[2]), "+f"(c[3])
                 : "r"(a[0]), "r"(a[1]), "r"(a[2]), "r"(a[3]), "r"(b0), "r"(b1));
}

// ---------------------------------------------------------------- k_prep
__global__ void k_prep(const float* __restrict__ x) {
    int p = blockIdx.x * blockDim.x + threadIdx.x;
    if (p < MTOT) {
        const float4* r = (const float4*)(x + (size_t)p * CIN);
        __nv_bfloat162* hi = (__nv_bfloat162*)(g_xhi + (size_t)p * CIN);
        __nv_bfloat162* lo = (__nv_bfloat162*)(g_xlo + (size_t)p * CIN);
        float s = 0.f;
        #pragma unroll
        for (int i = 0; i < CIN / 4; i++) {
            float4 v = r[i];
            s += v.x * v.x + v.y * v.y + v.z * v.z + v.w * v.w;
            __nv_bfloat16 hx = __float2bfloat16(v.x), hy = __float2bfloat16(v.y);
            __nv_bfloat16 hz = __float2bfloat16(v.z), hw = __float2bfloat16(v.w);
            hi[2 * i]     = __nv_bfloat162(hx, hy);
            hi[2 * i + 1] = __nv_bfloat162(hz, hw);
            lo[2 * i]     = __nv_bfloat162(__float2bfloat16(v.x - __bfloat162float(hx)),
                                           __float2bfloat16(v.y - __bfloat162float(hy)));
            lo[2 * i + 1] = __nv_bfloat162(__float2bfloat16(v.z - __bfloat162float(hz)),
                                           __float2bfloat16(v.w - __bfloat162float(hw)));
        }
        g_sqnorm[p] = s;
    }
    if (p < COUT) { g_sum[p] = 0.f; g_sumsq[p] = 0.f; }
}

// ---------------------------------------------------------------- k_knn_pool
// grid (NPTS/QT, BSZ), 256 threads / 8 warps.
__global__ __launch_bounds__(256, 2)
void k_knn_pool(const float* __restrict__ x) {
    extern __shared__ char smem[];
    const uint32_t sb = smem_u32(smem);
    float* Ss    = (float*)(smem + OFF_SS);
    float* sqc_s = (float*)(smem + OFF_SQC);

    const int tid  = threadIdx.x;
    const int wid  = tid >> 5, lane = tid & 31;
    const int b    = blockIdx.y;
    const int q0   = blockIdx.x * QT;
    const int mrow0 = (wid & 3) * 32;       // warp's query rows
    const int ncol0 = (wid >> 2) * 32;      // warp's candidate cols

    // ldmatrix per-lane row/col selectors
    const int rowselA = (lane & 7) + ((lane >> 3) & 1) * 8;
    const int kpA     = (lane >> 4) * 8;
    const int nbB     = (lane & 7) + ((lane >> 4) & 1) * 8;
    const int kbB     = ((lane >> 3) & 1) * 8;

    // load query hi/lo tiles once: 128 rows x 128 B
    {
        const char* ahi = (const char*)(g_xhi + (size_t)(b * NPTS + q0) * CIN);
        const char* alo = (const char*)(g_xlo + (size_t)(b * NPTS + q0) * CIN);
        #pragma unroll
        for (int it = 0; it < 4; it++) {
            int id = tid + it * 256;                 // 0..1023
            int row = id >> 3, ch = (id & 7) * 16;
            int so = row * 144 + ch, go = row * 128 + ch;
            *(uint4*)(smem + OFF_AHI + so) = *(const uint4*)(ahi + go);
            *(uint4*)(smem + OFF_ALO + so) = *(const uint4*)(alo + go);
        }
    }

    float kval[KNN]; int kidx[KNN];
    #pragma unroll
    for (int i = 0; i < KNN; i++) { kval[i] = 3.4e38f; kidx[i] = 0; }

    const int qrow = tid & 127;          // query this thread scans
    const int half = tid >> 7;           // which 32-candidate half

    for (int tile = 0; tile < NTILE; ++tile) {
        // fill candidate tiles: 64 rows x 128 B (hi/lo) + sqnorms
        {
            const char* bhi = (const char*)(g_xhi + (size_t)(b * NPTS + tile * CT) * CIN);
            const char* blo = (const char*)(g_xlo + (size_t)(b * NPTS + tile * CT) * CIN);
            #pragma unroll
            for (int it = 0; it < 2; it++) {
                int id = tid + it * 256;             // 0..511
                int row = id >> 3, ch = (id & 7) * 16;
                int so = row * 144 + ch, go = row * 128 + ch;
                *(uint4*)(smem + OFF_BHI + so) = *(const uint4*)(bhi + go);
                *(uint4*)(smem + OFF_BLO + so) = *(const uint4*)(blo + go);
            }
            if (tid < CT) sqc_s[tid] = g_sqnorm[b * NPTS + tile * CT + tid];
        }
        __syncthreads();

        // 128x64 score tile per CTA, 32x32 per warp, 3 passes (HH, HL, LH), K=64
        float c[2][4][4];
        #pragma unroll
        for (int mi = 0; mi < 2; mi++)
            #pragma unroll
            for (int ni = 0; ni < 4; ni++)
                #pragma unroll
                for (int t = 0; t < 4; t++) c[mi][ni][t] = 0.f;

        const uint32_t aBase[3] = { sb + OFF_AHI, sb + OFF_AHI, sb + OFF_ALO };
        const uint32_t bBase[3] = { sb + OFF_BHI, sb + OFF_BLO, sb + OFF_BHI };

        #pragma unroll
        for (int pass = 0; pass < 3; ++pass) {
            uint32_t ab = aBase[pass], bb = bBase[pass];
            #pragma unroll
            for (int kk = 0; kk < 4; ++kk) {
                uint32_t afr[2][4];
                #pragma unroll
                for (int mi = 0; mi < 2; mi++) {
                    uint32_t addr = ab + (uint32_t)((mrow0 + mi * 16 + rowselA) * 144
                                                    + (kk * 16 + kpA) * 2);
                    ldmx4(afr[mi][0], afr[mi][1], afr[mi][2], afr[mi][3], addr);
                }
                uint32_t bfr[8];
                #pragma unroll
                for (int ng = 0; ng < 2; ng++) {
                    uint32_t addr = bb + (uint32_t)((ncol0 + ng * 16 + nbB) * 144
                                                    + (kk * 16 + kbB) * 2);
                    ldmx4(bfr[ng * 4 + 0], bfr[ng * 4 + 1],
                          bfr[ng * 4 + 2], bfr[ng * 4 + 3], addr);
                }
                #pragma unroll
                for (int mi = 0; mi < 2; mi++)
                    #pragma unroll
                    for (int ni = 0; ni < 4; ni++)
                        mma16816(c[mi][ni], afr[mi], bfr[ni * 2], bfr[ni * 2 + 1]);
            }
        }

        // write keys = ||x_c||^2 - 2*dot into Ss
        {
            int r0 = mrow0 + (lane >> 2);
            int cn = ncol0 + (lane & 3) * 2;
            #pragma unroll
            for (int ni = 0; ni < 4; ni++) {
                int cc = cn + ni * 8;
                float s0 = sqc_s[cc], s1 = sqc_s[cc + 1];
                #pragma unroll
                for (int mi = 0; mi < 2; mi++) {
                    int ra = r0 + mi * 16;
                    Ss[ra * PAD_S + cc]           = fmaf(-2.f, c[mi][ni][0], s0);
                    Ss[ra * PAD_S + cc + 1]       = fmaf(-2.f, c[mi][ni][1], s1);
                    Ss[(ra + 8) * PAD_S + cc]     = fmaf(-2.f, c[mi][ni][2], s0);
                    Ss[(ra + 8) * PAD_S + cc + 1] = fmaf(-2.f, c[mi][ni][3], s1);
                }
            }
        }
        __syncthreads();

        // split streaming top-16 (filter): thread scans its 32-candidate half
        {
            int base = tile * CT + half * 32;
            const float* row = Ss + qrow * PAD_S + half * 32;
            #pragma unroll 8
            for (int j = 0; j < 32; j++) {
                float key = row[j];
                if (key < kval[KNN - 1]) {
                    kval[KNN - 1] = key; kidx[KNN - 1] = base + j;
                    #pragma unroll
                    for (int t = KNN - 1; t > 0; --t) {
                        if (kval[t] < kval[t - 1]) {
                            float tv = kval[t]; kval[t] = kval[t - 1]; kval[t - 1] = tv;
                            int   ti = kidx[t]; kidx[t] = kidx[t - 1]; kidx[t - 1] = ti;
                        }
                    }
                }
            }
        }
        __syncthreads();
    }

    // ---- refine: union of the two half top-16 lists -> exact fp32 keys ----
    int*   cand = (int*)(smem + OFF_SS);            // [128][32]  16 KB
    float* rkey = (float*)(smem + OFF_SS + 16384);  // [128][32]  16 KB
    {
        int base = qrow * 32 + half * 16;
        #pragma unroll
        for (int i = 0; i < KNN; i++) cand[base + i] = kidx[i];
    }
    __syncthreads();

    const float* xb = x + (size_t)b * NPTS * CIN;
    for (int u = tid; u < QT * 32; u += 256) {
        int q = u >> 5, ci = u & 31;
        int nb = cand[q * 32 + ci];
        const float4* qr = (const float4*)(xb + (size_t)(q0 + q) * CIN);
        const float4* cr = (const float4*)(xb + (size_t)nb * CIN);
        float d = 0.f;
        #pragma unroll
        for (int i = 0; i < CIN / 4; i++) {
            float4 a = qr[i], cc = cr[i];
            d = fmaf(a.x, cc.x, d); d = fmaf(a.y, cc.y, d);
            d = fmaf(a.z, cc.z, d); d = fmaf(a.w, cc.w, d);
        }
        rkey[u] = fmaf(-2.f, d, g_sqnorm[b * NPTS + nb]);
    }
    __syncthreads();

    // select exact top-16 of the 32 (set only; maxpool ignores order)
    int* sidx = (int*)(smem + OFF_BHI);             // [128][16]
    if (tid < QT) {
        float sv[KNN]; int si[KNN];
        #pragma unroll
        for (int i = 0; i < KNN; i++) { sv[i] = 3.4e38f; si[i] = 0x7fffffff; }
        const float* rk = rkey + tid * 32;
        const int*   cd = cand + tid * 32;
        #pragma unroll 4
        for (int j = 0; j < 32; j++) {
            float key = rk[j]; int id = cd[j];
            bool adm = (key < sv[KNN - 1]) || (key == sv[KNN - 1] && id < si[KNN - 1]);
            if (adm) {
                sv[KNN - 1] = key; si[KNN - 1] = id;
                #pragma unroll
                for (int t = KNN - 1; t > 0; --t) {
                    bool sw = (sv[t] < sv[t - 1]) ||
                              (sv[t] == sv[t - 1] && si[t] < si[t - 1]);
                    if (sw) {
                        float tv = sv[t]; sv[t] = sv[t - 1]; sv[t - 1] = tv;
                        int   ti = si[t]; si[t] = si[t - 1]; si[t - 1] = ti;
                    }
                }
            }
        }
        #pragma unroll
        for (int i = 0; i < KNN; i++) sidx[tid * KNN + i] = si[i];
    }
    __syncthreads();

    // warp-cooperative gather + maxpool (coalesced row loads)
    for (int qq = wid * 16; qq < wid * 16 + 16; ++qq) {
        float m0 = -3.4e38f, m1 = -3.4e38f;
        #pragma unroll
        for (int i = 0; i < KNN; i++) {
            int nb = sidx[qq * KNN + i];
            const float* row = xb + (size_t)nb * CIN;
            m0 = fmaxf(m0, row[lane]);
            m1 = fmaxf(m1, row[lane + 32]);
        }
        float* outp = g_pooled + (size_t)(b * NPTS + q0 + qq) * CIN;
        outp[lane] = m0; outp[lane + 32] = m1;
    }
}

// ---------------------------------------------------------------- k_gemm_stats
__global__ __launch_bounds__(256)
void k_gemm_stats(const float* __restrict__ W, const float* __restrict__ bias,
                  float* __restrict__ out) {
    extern __shared__ float sh[];
    float* Ps   = sh;                     // [128][PAD_A]
    float* Ws   = Ps + 128 * PAD_A;       // [128][PAD_A]
    float* ssum = Ws + 128 * PAD_A;
    float* ssq  = ssum + COUT;

    const int tid = threadIdx.x;
    const int tx = tid & 15, ty = tid >> 4;
    const int row0 = blockIdx.x * 128;

    {
        const float4* src = (const float4*)(g_pooled + (size_t)row0 * CIN);
        #pragma unroll
        for (int t = 0; t < 8; t++) {
            int id = tid + t * 256;
            int r = id >> 4, c4 = (id & 15) << 2;
            *(float4*)&Ps[r * PAD_A + c4] = src[id];
        }
        const float4* wsrc = (const float4*)W;
        #pragma unroll
        for (int t = 0; t < 8; t++) {
            int id = tid + t * 256;
            int r = id >> 4, c4 = (id & 15) << 2;
            *(float4*)&Ws[r * PAD_A + c4] = wsrc[id];
        }
        if (tid < COUT) { ssum[tid] = 0.f; ssq[tid] = 0.f; }
    }
    __syncthreads();

    float acc[8][8];
    #pragma unroll
    for (int i = 0; i < 8; i++)
        #pragma unroll
        for (int j = 0; j < 8; j++) acc[i][j] = 0.f;

    #pragma unroll 4
    for (int k = 0; k < CIN; k++) {
        float a[8], bb[8];
        #pragma unroll
        for (int i = 0; i < 8; i++) a[i] = Ps[(ty + 16 * i) * PAD_A + k];
        #pragma unroll
        for (int j = 0; j < 8; j++) bb[j] = Ws[(tx + 16 * j) * PAD_A + k];
        #pragma unroll
        for (int i = 0; i < 8; i++)
            #pragma unroll
            for (int j = 0; j < 8; j++)
                acc[i][j] = fmaf(a[i], bb[j], acc[i][j]);
    }

    float ls[8], lq[8];
    #pragma unroll
    for (int j = 0; j < 8; j++) { ls[j] = 0.f; lq[j] = 0.f; }

    #pragma unroll
    for (int j = 0; j < 8; j++) {
        int c = tx + 16 * j;
        float bj = bias[c];
        #pragma unroll
        for (int i = 0; i < 8; i++) {
            float y = acc[i][j] + bj;
            out[(size_t)(row0 + ty + 16 * i) * COUT + c] = y;
            ls[j] += y;
            lq[j] = fmaf(y, y, lq[j]);
        }
    }
    #pragma unroll
    for (int j = 0; j < 8; j++) {
        int c = tx + 16 * j;
        atomicAdd(&ssum[c], ls[j]);
        atomicAdd(&ssq[c],  lq[j]);
    }
    __syncthreads();
    if (tid < COUT) {
        atomicAdd(&g_sum[tid],   ssum[tid]);
        atomicAdd(&g_sumsq[tid], ssq[tid]);
    }
}

// ---------------------------------------------------------------- k_finalize
__global__ void k_finalize(const float* __restrict__ gamma,
                           const float* __restrict__ beta) {
    int c = threadIdx.x;
    if (c < COUT) {
        const float invM = 1.f / (float)MTOT;
        float m = g_sum[c] * invM;
        float v = fmaf(-m, m, g_sumsq[c] * invM);
        float sc = gamma[c] * rsqrtf(v + 1e-5f);
        g_scale[c] = sc;
        g_shift[c] = fmaf(-m, sc, beta[c]);
    }
}

// ---------------------------------------------------------------- k_apply
__global__ void k_apply(float* __restrict__ out) {
    int i = blockIdx.x * blockDim.x + threadIdx.x;
    if (i < MTOT * COUT / 4) {
        float4 v = ((float4*)out)[i];
        int c = (i * 4) & (COUT - 1);
        v.x = fmaxf(0.f, fmaf(v.x, g_scale[c],     g_shift[c]));
        v.y = fmaxf(0.f, fmaf(v.y, g_scale[c + 1], g_shift[c + 1]));
        v.z = fmaxf(0.f, fmaf(v.z, g_scale[c + 2], g_shift[c + 2]));
        v.w = fmaxf(0.f, fmaf(v.w, g_scale[c + 3], g_shift[c + 3]));
        ((float4*)out)[i] = v;
    }
}

// ---------------------------------------------------------------- launch
extern "C" void kernel_launch(void* const* d_in, const int* in_sizes, int n_in,
                              void* d_out, int out_size) {
    const float* x     = (const float*)d_in[0];
    const float* W     = (const float*)d_in[1];
    const float* bias  = (const float*)d_in[2];
    const float* gamma = (const float*)d_in[3];
    const float* beta  = (const float*)d_in[4];
    float* out = (float*)d_out;

    const int smem2 = (128 * PAD_A * 2 + 2 * COUT) * 4;
    cudaFuncSetAttribute(k_knn_pool,   cudaFuncAttributeMaxDynamicSharedMemorySize, SMEM_K1);
    cudaFuncSetAttribute(k_gemm_stats, cudaFuncAttributeMaxDynamicSharedMemorySize, smem2);

    k_prep<<<(MTOT + 255) / 256, 256>>>(x);
    k_knn_pool<<<dim3(NPTS / QT, BSZ), 256, SMEM_K1>>>(x);
    k_gemm_stats<<<MTOT / 128, 256, smem2>>>(W, bias, out);
    k_finalize<<<1, COUT>>>(gamma, beta);
    k_apply<<<(MTOT * COUT / 4 + 255) / 256, 256>>>(out);
}